// round 2
// baseline (speedup 1.0000x reference)
#include <cuda_runtime.h>
#include <cuda_bf16.h>
#include <math_constants.h>

// Problem constants (fixed by setup_inputs)
#define B_   4
#define N_   8192
#define BN_  (B_ * N_)      // 32768 points
#define DIN  64
#define DPRE 67             // feature(64) + xyz(3)
#define C_   128            // D_OUT
#define K_   36

// ---------------- device scratch (no allocations allowed) ----------------
__device__ float g_EP [BN_ * C_];   // exp(Wr_left @ pre)
__device__ float g_EQ [BN_ * C_];   // exp((Wr_right - Wr_left) @ pre + br)
__device__ float g_V  [BN_ * C_];   // relu(Wv @ pre + bv)
__device__ int   g_idx[BN_ * K_];   // knn indices (global point index)
__device__ float g_mid[BN_ * C_];   // pre-projection attention output

// ---------------- fast exp (FMA pipe, avoids MUFU throughput wall) -------
__device__ __forceinline__ float fast_exp(float x) {
    float y = x * 1.4426950408889634f;      // x * log2(e)
    int   e = __float2int_rn(y);
    float f = y - (float)e;                 // f in [-0.5, 0.5]
    float p =            1.5403530393381609e-4f;
    p = fmaf(p, f, 1.3333558146428443e-3f);
    p = fmaf(p, f, 9.6181291076284770e-3f);
    p = fmaf(p, f, 5.5504108664821580e-2f);
    p = fmaf(p, f, 2.4022650695910070e-1f);
    p = fmaf(p, f, 6.9314718055994530e-1f);
    p = fmaf(p, f, 1.0f);
    float s = __int_as_float((e + 127) << 23);
    return p * s;
}

// ============================================================================
// Kernel 1: per-point preprocessing. 128 threads (4 warps), warp covers all
// 128 channels (4/lane), 4 points per warp iteration. Weights staged in smem
// transposed to [d][c] for float4 loads.
// smem: sWA|sWB|sWC (3 * 67*128 floats) + spre (4 warps * 4 pts * 68)
// ============================================================================
#define PREP_SMEM ((3 * DPRE * C_ + 4 * 4 * 68) * 4)

__global__ void prep_kernel(const float* __restrict__ feat,
                            const float* __restrict__ xyz,
                            const float* __restrict__ Wr,
                            const float* __restrict__ br,
                            const float* __restrict__ Wv,
                            const float* __restrict__ bv) {
    extern __shared__ float sm[];
    float* sWA = sm;                       // Wr_left   [d][c]
    float* sWB = sm + DPRE * C_;           // Wr_right  [d][c] (then -= left)
    float* sWC = sm + 2 * DPRE * C_;       // Wv        [d][c]
    float* sPre = sm + 3 * DPRE * C_;      // [warp][4][68]

    int t = threadIdx.x;
    // coalesced global reads, transposed smem writes
    for (int i = t; i < C_ * 134; i += 128) {
        int c = i / 134, dd = i % 134;
        float v = Wr[i];
        if (dd < DPRE) sWA[dd * C_ + c] = v;
        else           sWB[(dd - DPRE) * C_ + c] = v;
    }
    for (int i = t; i < C_ * DPRE; i += 128) {
        int c = i / DPRE, d = i % DPRE;
        sWC[d * C_ + c] = Wv[i];
    }
    __syncthreads();
    for (int i = t; i < DPRE * C_; i += 128) sWB[i] -= sWA[i];
    __syncthreads();

    int w = t >> 5, lane = t & 31;
    float4 br4 = *(const float4*)&br[4 * lane];
    float4 bv4 = *(const float4*)&bv[4 * lane];
    float* spw = sPre + w * 4 * 68;

    int base = blockIdx.x * 128 + w * 32;   // 32 points per warp
    for (int it = 0; it < 8; it++) {
        int m0 = base + it * 4;
        // stage pre = [feature, xyz] for 4 points
        #pragma unroll
        for (int p = 0; p < 4; p++) {
            int m = m0 + p;
            spw[p * 68 + lane]      = feat[(size_t)m * 64 + lane];
            spw[p * 68 + 32 + lane] = feat[(size_t)m * 64 + 32 + lane];
            if (lane < 3) spw[p * 68 + 64 + lane] = xyz[(size_t)m * 3 + lane];
        }
        __syncwarp();

        float aP[4][4], aQ[4][4], aV[4][4];
        #pragma unroll
        for (int p = 0; p < 4; p++)
            #pragma unroll
            for (int r = 0; r < 4; r++) { aP[p][r] = 0.f; aQ[p][r] = 0.f; aV[p][r] = 0.f; }

        for (int d = 0; d < DPRE; d++) {
            float4 wa = *(float4*)&sWA[d * C_ + 4 * lane];
            float4 wb = *(float4*)&sWB[d * C_ + 4 * lane];
            float4 wc = *(float4*)&sWC[d * C_ + 4 * lane];
            #pragma unroll
            for (int p = 0; p < 4; p++) {
                float x = spw[p * 68 + d];
                aP[p][0] = fmaf(wa.x, x, aP[p][0]);
                aP[p][1] = fmaf(wa.y, x, aP[p][1]);
                aP[p][2] = fmaf(wa.z, x, aP[p][2]);
                aP[p][3] = fmaf(wa.w, x, aP[p][3]);
                aQ[p][0] = fmaf(wb.x, x, aQ[p][0]);
                aQ[p][1] = fmaf(wb.y, x, aQ[p][1]);
                aQ[p][2] = fmaf(wb.z, x, aQ[p][2]);
                aQ[p][3] = fmaf(wb.w, x, aQ[p][3]);
                aV[p][0] = fmaf(wc.x, x, aV[p][0]);
                aV[p][1] = fmaf(wc.y, x, aV[p][1]);
                aV[p][2] = fmaf(wc.z, x, aV[p][2]);
                aV[p][3] = fmaf(wc.w, x, aV[p][3]);
            }
        }
        #pragma unroll
        for (int p = 0; p < 4; p++) {
            size_t m = (size_t)(m0 + p);
            float4 ep, eq, vv;
            ep.x = fast_exp(aP[p][0]); ep.y = fast_exp(aP[p][1]);
            ep.z = fast_exp(aP[p][2]); ep.w = fast_exp(aP[p][3]);
            eq.x = fast_exp(aQ[p][0] + br4.x); eq.y = fast_exp(aQ[p][1] + br4.y);
            eq.z = fast_exp(aQ[p][2] + br4.z); eq.w = fast_exp(aQ[p][3] + br4.w);
            vv.x = fmaxf(aV[p][0] + bv4.x, 0.f); vv.y = fmaxf(aV[p][1] + bv4.y, 0.f);
            vv.z = fmaxf(aV[p][2] + bv4.z, 0.f); vv.w = fmaxf(aV[p][3] + bv4.w, 0.f);
            *(float4*)&g_EP[m * C_ + 4 * lane] = ep;
            *(float4*)&g_EQ[m * C_ + 4 * lane] = eq;
            *(float4*)&g_V [m * C_ + 4 * lane] = vv;
        }
        __syncwarp();
    }
}

// ============================================================================
// Kernel 2: exact 36-NN. Thread-per-query, candidate tiles in smem (broadcast
// float4 loads), per-thread max-heap of 36 in smem with [slot][tid] layout
// (conflict-free), root cached in a register.
// ============================================================================
#define KNN_BT   128
#define KNN_CH   512

__global__ void knn_kernel(const float* __restrict__ xyz, int* __restrict__ outidx) {
    __shared__ float4 scand[KNN_CH];
    __shared__ float  hD[K_ * KNN_BT];
    __shared__ int    hI[K_ * KNN_BT];

    int t  = threadIdx.x;
    int b  = blockIdx.y;
    int qi = blockIdx.x * KNN_BT + t;
    const float* xb = xyz + (size_t)b * N_ * 3;

    float qx = xb[qi * 3 + 0], qy = xb[qi * 3 + 1], qz = xb[qi * 3 + 2];
    float sqq = qx * qx + qy * qy + qz * qz;

    #pragma unroll
    for (int s = 0; s < K_; s++) hD[s * KNN_BT + t] = CUDART_INF_F;
    float rootv = CUDART_INF_F;

    for (int cb = 0; cb < N_; cb += KNN_CH) {
        __syncthreads();
        for (int i = t; i < KNN_CH; i += KNN_BT) {
            const float* cp = xb + (size_t)(cb + i) * 3;
            float x = cp[0], y = cp[1], z = cp[2];
            scand[i] = make_float4(x, y, z, x * x + y * y + z * z);
        }
        __syncthreads();

        #pragma unroll 4
        for (int i = 0; i < KNN_CH; i++) {
            float4 c = scand[i];
            float dot = fmaf(c.z, qz, fmaf(c.y, qy, c.x * qx));
            float d   = fmaf(-2.f, dot, sqq + c.w);
            if (d < rootv) {
                int jg = b * N_ + cb + i;
                int h = 0;
                for (;;) {
                    int l = 2 * h + 1;
                    if (l >= K_) break;
                    float dc = hD[l * KNN_BT + t];
                    int child = l;
                    if (l + 1 < K_) {
                        float dr = hD[(l + 1) * KNN_BT + t];
                        if (dr > dc) { dc = dr; child = l + 1; }
                    }
                    if (dc <= d) break;
                    hD[h * KNN_BT + t] = dc;
                    hI[h * KNN_BT + t] = hI[child * KNN_BT + t];
                    h = child;
                }
                hD[h * KNN_BT + t] = d;
                hI[h * KNN_BT + t] = jg;
                rootv = hD[t];
            }
        }
    }
    int qg = b * N_ + qi;
    #pragma unroll
    for (int s = 0; s < K_; s++) outidx[(size_t)qg * K_ + s] = hI[s * KNN_BT + t];
}

// ============================================================================
// Kernel 3: vector attention accumulate. Warp per query, 4 channels/lane.
// unnorm weight = EP[j][c] * EQ[q][c]; softmax denom via shfl reduce.
// ============================================================================
__global__ void attn_kernel(const int* __restrict__ idx, float* __restrict__ mid) {
    int gw   = (blockIdx.x * blockDim.x + threadIdx.x) >> 5;
    int lane = threadIdx.x & 31;
    if (gw >= BN_) return;
    size_t q = (size_t)gw;

    float4 eq = *(const float4*)&g_EQ[q * C_ + 4 * lane];
    int i0 = idx[q * K_ + lane];
    int i1 = (lane < K_ - 32) ? idx[q * K_ + 32 + lane] : 0;

    float4 acc = make_float4(0.f, 0.f, 0.f, 0.f);
    #pragma unroll 4
    for (int k = 0; k < K_; k++) {
        int j = (k < 32) ? __shfl_sync(0xffffffffu, i0, k)
                         : __shfl_sync(0xffffffffu, i1, k - 32);
        float4 ep = *(const float4*)&g_EP[(size_t)j * C_ + 4 * lane];
        float4 v  = *(const float4*)&g_V [(size_t)j * C_ + 4 * lane];
        float wx = ep.x * eq.x, wy = ep.y * eq.y, wz = ep.z * eq.z, ww = ep.w * eq.w;
        float part = (wx + wy) + (wz + ww);
        part += __shfl_xor_sync(0xffffffffu, part, 16);
        part += __shfl_xor_sync(0xffffffffu, part, 8);
        part += __shfl_xor_sync(0xffffffffu, part, 4);
        part += __shfl_xor_sync(0xffffffffu, part, 2);
        part += __shfl_xor_sync(0xffffffffu, part, 1);
        float rinv = __fdividef(1.0f, part);
        acc.x = fmaf(v.x, wx * rinv, acc.x);
        acc.y = fmaf(v.y, wy * rinv, acc.y);
        acc.z = fmaf(v.z, wz * rinv, acc.z);
        acc.w = fmaf(v.w, ww * rinv, acc.w);
    }
    *(float4*)&mid[q * C_ + 4 * lane] = acc;
}

// ============================================================================
// Kernel 4: output projection  out = mid @ Ws^T + bs.
// Ws cached in smem transposed [c][d] (stride 132), 8 queries per warp.
// ============================================================================
#define WS_STRIDE 132
#define OUT_SMEM  ((C_ * WS_STRIDE + 8 * C_ * 9) * 4)

__global__ void outproj_kernel(const float* __restrict__ Ws,
                               const float* __restrict__ bs,
                               float* __restrict__ out) {
    extern __shared__ float sm[];
    float* sWs  = sm;                    // [c][d] stride WS_STRIDE
    float* sMid = sm + C_ * WS_STRIDE;   // [warp][c][9]

    int t = threadIdx.x, w = t >> 5, lane = t & 31;
    for (int i = t; i < C_ * C_; i += 256) {
        int d = i >> 7, c = i & 127;
        sWs[c * WS_STRIDE + d] = Ws[i];
    }
    __syncthreads();

    float4 bs4 = *(const float4*)&bs[4 * lane];
    float* smw = sMid + w * C_ * 9;
    int gw = blockIdx.x * 8 + w;                 // 1024 warps total

    for (int itq = 0; itq < 4; itq++) {
        int q0 = (gw + itq * 1024) * 8;
        #pragma unroll
        for (int p = 0; p < 8; p++) {
            float4 m4 = *(const float4*)&g_mid[(size_t)(q0 + p) * C_ + 4 * lane];
            smw[(4 * lane + 0) * 9 + p] = m4.x;
            smw[(4 * lane + 1) * 9 + p] = m4.y;
            smw[(4 * lane + 2) * 9 + p] = m4.z;
            smw[(4 * lane + 3) * 9 + p] = m4.w;
        }
        __syncwarp();
        float4 acc[8];
        #pragma unroll
        for (int p = 0; p < 8; p++) acc[p] = bs4;
        for (int c = 0; c < C_; c++) {
            float4 wr = *(float4*)&sWs[c * WS_STRIDE + 4 * lane];
            #pragma unroll
            for (int p = 0; p < 8; p++) {
                float mc = smw[c * 9 + p];
                acc[p].x = fmaf(wr.x, mc, acc[p].x);
                acc[p].y = fmaf(wr.y, mc, acc[p].y);
                acc[p].z = fmaf(wr.z, mc, acc[p].z);
                acc[p].w = fmaf(wr.w, mc, acc[p].w);
            }
        }
        #pragma unroll
        for (int p = 0; p < 8; p++)
            *(float4*)&out[(size_t)(q0 + p) * C_ + 4 * lane] = acc[p];
        __syncwarp();
    }
}

// ============================================================================
extern "C" void kernel_launch(void* const* d_in, const int* in_sizes, int n_in,
                              void* d_out, int out_size) {
    const float* feat = (const float*)d_in[0];
    const float* xyz  = (const float*)d_in[1];
    const float* Wr   = (const float*)d_in[2];
    const float* br   = (const float*)d_in[3];
    const float* Wv   = (const float*)d_in[4];
    const float* bv   = (const float*)d_in[5];
    const float* Ws   = (const float*)d_in[6];
    const float* bs   = (const float*)d_in[7];
    float* out = (float*)d_out;

    cudaFuncSetAttribute(prep_kernel, cudaFuncAttributeMaxDynamicSharedMemorySize, PREP_SMEM);
    cudaFuncSetAttribute(outproj_kernel, cudaFuncAttributeMaxDynamicSharedMemorySize, OUT_SMEM);

    // 1) per-point EP/EQ/V
    prep_kernel<<<BN_ / 128, 128, PREP_SMEM>>>(feat, xyz, Wr, br, Wv, bv);

    // 2) exact 36-NN
    int* idxp;
    cudaGetSymbolAddress((void**)&idxp, g_idx);
    {
        dim3 grid(N_ / KNN_BT, B_);
        knn_kernel<<<grid, KNN_BT>>>(xyz, idxp);
    }

    // 3) vector attention accumulate
    float* midp;
    cudaGetSymbolAddress((void**)&midp, g_mid);
    attn_kernel<<<BN_ / 8, 256>>>(idxp, midp);

    // 4) output projection
    outproj_kernel<<<128, 256, OUT_SMEM>>>(Ws, bs, out);
}

// round 4
// speedup vs baseline: 3.3282x; 3.3282x over previous
#include <cuda_runtime.h>
#include <cuda_bf16.h>
#include <math_constants.h>

// Problem constants (fixed by setup_inputs)
#define B_   4
#define N_   8192
#define BN_  (B_ * N_)      // 32768 points
#define DIN  64
#define DPRE 67             // feature(64) + xyz(3)
#define C_   128            // D_OUT
#define K_   36

// spatial grid
#define G_   16
#define GC_  (G_ * G_ * G_)   // 4096 cells per batch

// ---------------- device scratch (no allocations allowed) ----------------
__device__ float  g_EP [BN_ * C_];   // exp(Wr_left @ pre)           (sorted order)
__device__ float  g_EQ [BN_ * C_];   // exp((Wr_r - Wr_l) @ pre + br)(sorted order)
__device__ float  g_V  [BN_ * C_];   // relu(Wv @ pre + bv)          (sorted order)
__device__ float  g_mid[BN_ * C_];   // attention output             (sorted order)
__device__ int    g_nbr[BN_ * K_];   // knn neighbor SORTED positions
__device__ int    g_cellcnt [B_ * GC_];
__device__ int    g_cellstart[B_ * GC_];
__device__ int    g_cellid[BN_];     // per original point: within-batch cell
__device__ int    g_rank  [BN_];     // atomic rank within cell (pre-sort)
__device__ float4 g_pts4 [BN_];      // sorted points (x,y,z,pad)
__device__ int    g_pid  [BN_];      // sorted pos -> original global id
__device__ int    g_spos [BN_];      // original global id -> sorted pos

// ---------------- fast exp (FMA pipe) ------------------------------------
__device__ __forceinline__ float fast_exp(float x) {
    float y = x * 1.4426950408889634f;      // x * log2(e)
    int   e = __float2int_rn(y);
    float f = y - (float)e;                 // f in [-0.5, 0.5]
    float p =            1.5403530393381609e-4f;
    p = fmaf(p, f, 1.3333558146428443e-3f);
    p = fmaf(p, f, 9.6181291076284770e-3f);
    p = fmaf(p, f, 5.5504108664821580e-2f);
    p = fmaf(p, f, 2.4022650695910070e-1f);
    p = fmaf(p, f, 6.9314718055994530e-1f);
    p = fmaf(p, f, 1.0f);
    float s = __int_as_float((e + 127) << 23);
    return p * s;
}

// ============================================================================
// Grid build step 1: cell assignment + per-cell atomic rank
// ============================================================================
__global__ void cellassign_kernel(const float* __restrict__ xyz) {
    int m = blockIdx.x * blockDim.x + threadIdx.x;
    if (m >= BN_) return;
    int b = m >> 13;
    float x = xyz[(size_t)m * 3 + 0];
    float y = xyz[(size_t)m * 3 + 1];
    float z = xyz[(size_t)m * 3 + 2];
    int cx = min(G_ - 1, max(0, (int)(x * (float)G_)));
    int cy = min(G_ - 1, max(0, (int)(y * (float)G_)));
    int cz = min(G_ - 1, max(0, (int)(z * (float)G_)));
    int cell = (cx * G_ + cy) * G_ + cz;
    int r = atomicAdd(&g_cellcnt[b * GC_ + cell], 1);
    g_cellid[m] = cell;
    g_rank[m] = r;
}

// ============================================================================
// Grid build step 2: exclusive prefix sum over 4096 cells (one block / batch)
// ============================================================================
__global__ void scan_kernel() {
    __shared__ int s[1024];
    int b = blockIdx.x;
    int t = threadIdx.x;
    int c0 = g_cellcnt[b * GC_ + 4 * t + 0];
    int c1 = g_cellcnt[b * GC_ + 4 * t + 1];
    int c2 = g_cellcnt[b * GC_ + 4 * t + 2];
    int c3 = g_cellcnt[b * GC_ + 4 * t + 3];
    int tot = c0 + c1 + c2 + c3;
    s[t] = tot;
    __syncthreads();
    for (int off = 1; off < 1024; off <<= 1) {
        int x = (t >= off) ? s[t - off] : 0;
        __syncthreads();
        s[t] += x;
        __syncthreads();
    }
    int excl = s[t] - tot;
    g_cellstart[b * GC_ + 4 * t + 0] = excl;
    g_cellstart[b * GC_ + 4 * t + 1] = excl + c0;
    g_cellstart[b * GC_ + 4 * t + 2] = excl + c0 + c1;
    g_cellstart[b * GC_ + 4 * t + 3] = excl + c0 + c1 + c2;
}

// ============================================================================
// Grid build step 3: scatter points into cell-sorted layout
// ============================================================================
__global__ void scatter_kernel(const float* __restrict__ xyz) {
    int m = blockIdx.x * blockDim.x + threadIdx.x;
    if (m >= BN_) return;
    int b = m >> 13;
    int cell = g_cellid[m];
    int p = b * N_ + g_cellstart[b * GC_ + cell] + g_rank[m];
    float x = xyz[(size_t)m * 3 + 0];
    float y = xyz[(size_t)m * 3 + 1];
    float z = xyz[(size_t)m * 3 + 2];
    g_pts4[p] = make_float4(x, y, z, 0.0f);
    g_pid[p] = m;
}

// ============================================================================
// Grid build step 4: determinism fix-up (atomic rank order varies per replay;
// insertion-sort each cell by original index so layout is replay-invariant).
// ============================================================================
__global__ void sortfix_kernel() {
    int i = blockIdx.x * blockDim.x + threadIdx.x;
    if (i >= B_ * GC_) return;
    int b = i / GC_;
    int cell = i - b * GC_;
    int start = b * N_ + g_cellstart[b * GC_ + cell];
    int cnt = g_cellcnt[b * GC_ + cell];
    for (int a = 1; a < cnt; a++) {
        int pid = g_pid[start + a];
        float4 pt = g_pts4[start + a];
        int j = a - 1;
        while (j >= 0 && g_pid[start + j] > pid) {
            g_pid[start + j + 1]  = g_pid[start + j];
            g_pts4[start + j + 1] = g_pts4[start + j];
            j--;
        }
        g_pid[start + j + 1]  = pid;
        g_pts4[start + j + 1] = pt;
    }
    for (int a = 0; a < cnt; a++) g_spos[g_pid[start + a]] = start + a;
}

// ============================================================================
// Kernel: per-point preprocessing (EP/EQ/V), written in SORTED order for the
// attention gather's locality. Weights staged in smem transposed to [d][c].
// ============================================================================
#define PREP_SMEM ((3 * DPRE * C_ + 4 * 4 * 68) * 4)

__global__ void prep_kernel(const float* __restrict__ feat,
                            const float* __restrict__ xyz,
                            const float* __restrict__ Wr,
                            const float* __restrict__ br,
                            const float* __restrict__ Wv,
                            const float* __restrict__ bv) {
    extern __shared__ float sm[];
    float* sWA = sm;                       // Wr_left   [d][c]
    float* sWB = sm + DPRE * C_;           // Wr_right  [d][c] (then -= left)
    float* sWC = sm + 2 * DPRE * C_;       // Wv        [d][c]
    float* sPre = sm + 3 * DPRE * C_;      // [warp][4][68]

    int t = threadIdx.x;
    for (int i = t; i < C_ * 134; i += 128) {
        int c = i / 134, dd = i % 134;
        float v = Wr[i];
        if (dd < DPRE) sWA[dd * C_ + c] = v;
        else           sWB[(dd - DPRE) * C_ + c] = v;
    }
    for (int i = t; i < C_ * DPRE; i += 128) {
        int c = i / DPRE, d = i % DPRE;
        sWC[d * C_ + c] = Wv[i];
    }
    __syncthreads();
    for (int i = t; i < DPRE * C_; i += 128) sWB[i] -= sWA[i];
    __syncthreads();

    int w = t >> 5, lane = t & 31;
    float4 br4 = *(const float4*)&br[4 * lane];
    float4 bv4 = *(const float4*)&bv[4 * lane];
    float* spw = sPre + w * 4 * 68;

    int base = blockIdx.x * 128 + w * 32;   // 32 points per warp
    for (int it = 0; it < 8; it++) {
        int m0 = base + it * 4;
        #pragma unroll
        for (int p = 0; p < 4; p++) {
            int m = m0 + p;
            spw[p * 68 + lane]      = feat[(size_t)m * 64 + lane];
            spw[p * 68 + 32 + lane] = feat[(size_t)m * 64 + 32 + lane];
            if (lane < 3) spw[p * 68 + 64 + lane] = xyz[(size_t)m * 3 + lane];
        }
        __syncwarp();

        float aP[4][4], aQ[4][4], aV[4][4];
        #pragma unroll
        for (int p = 0; p < 4; p++)
            #pragma unroll
            for (int r = 0; r < 4; r++) { aP[p][r] = 0.f; aQ[p][r] = 0.f; aV[p][r] = 0.f; }

        for (int d = 0; d < DPRE; d++) {
            float4 wa = *(float4*)&sWA[d * C_ + 4 * lane];
            float4 wb = *(float4*)&sWB[d * C_ + 4 * lane];
            float4 wc = *(float4*)&sWC[d * C_ + 4 * lane];
            #pragma unroll
            for (int p = 0; p < 4; p++) {
                float x = spw[p * 68 + d];
                aP[p][0] = fmaf(wa.x, x, aP[p][0]);
                aP[p][1] = fmaf(wa.y, x, aP[p][1]);
                aP[p][2] = fmaf(wa.z, x, aP[p][2]);
                aP[p][3] = fmaf(wa.w, x, aP[p][3]);
                aQ[p][0] = fmaf(wb.x, x, aQ[p][0]);
                aQ[p][1] = fmaf(wb.y, x, aQ[p][1]);
                aQ[p][2] = fmaf(wb.z, x, aQ[p][2]);
                aQ[p][3] = fmaf(wb.w, x, aQ[p][3]);
                aV[p][0] = fmaf(wc.x, x, aV[p][0]);
                aV[p][1] = fmaf(wc.y, x, aV[p][1]);
                aV[p][2] = fmaf(wc.z, x, aV[p][2]);
                aV[p][3] = fmaf(wc.w, x, aV[p][3]);
            }
        }
        #pragma unroll
        for (int p = 0; p < 4; p++) {
            size_t sp = (size_t)g_spos[m0 + p];     // sorted destination
            float4 ep, eq, vv;
            ep.x = fast_exp(aP[p][0]); ep.y = fast_exp(aP[p][1]);
            ep.z = fast_exp(aP[p][2]); ep.w = fast_exp(aP[p][3]);
            eq.x = fast_exp(aQ[p][0] + br4.x); eq.y = fast_exp(aQ[p][1] + br4.y);
            eq.z = fast_exp(aQ[p][2] + br4.z); eq.w = fast_exp(aQ[p][3] + br4.w);
            vv.x = fmaxf(aV[p][0] + bv4.x, 0.f); vv.y = fmaxf(aV[p][1] + bv4.y, 0.f);
            vv.z = fmaxf(aV[p][2] + bv4.z, 0.f); vv.w = fmaxf(aV[p][3] + bv4.w, 0.f);
            *(float4*)&g_EP[sp * C_ + 4 * lane] = ep;
            *(float4*)&g_EQ[sp * C_ + 4 * lane] = eq;
            *(float4*)&g_V [sp * C_ + 4 * lane] = vv;
        }
        __syncwarp();
    }
}

// ============================================================================
// Kernel: exact 36-NN via grid ring expansion. Thread-per-query over SORTED
// points. DIRECT squared distance (dx^2+dy^2+dz^2) — no cancellation, so our
// ranking matches the true ranking; only the reference's own fp noise remains.
// Per-thread 36-max-heap in smem ([slot][tid], conflict-free).
// ============================================================================
#define KNN_BT 128

__global__ void knnq_kernel() {
    __shared__ float hD[K_ * KNN_BT];
    __shared__ int   hI[K_ * KNN_BT];

    int t = threadIdx.x;
    int p = blockIdx.x * KNN_BT + t;     // global sorted position (query)
    int b = p >> 13;

    float4 me = g_pts4[p];
    float qx = me.x, qy = me.y, qz = me.z;
    int cx = min(G_ - 1, max(0, (int)(qx * (float)G_)));
    int cy = min(G_ - 1, max(0, (int)(qy * (float)G_)));
    int cz = min(G_ - 1, max(0, (int)(qz * (float)G_)));

    #pragma unroll
    for (int s = 0; s < K_; s++) hD[s * KNN_BT + t] = CUDART_INF_F;
    float rootv = CUDART_INF_F;

    const float h = 1.0f / (float)G_;
    const int cbase = b * GC_;
    const int pbase = b * N_;

    for (int r = 0; r < G_; r++) {
        int lox = max(cx - r, 0), hix = min(cx + r, G_ - 1);
        int loy = max(cy - r, 0), hiy = min(cy + r, G_ - 1);
        int loz = max(cz - r, 0), hiz = min(cz + r, G_ - 1);

        for (int ix = lox; ix <= hix; ix++) {
            bool fx = (ix == cx - r) || (ix == cx + r);
            for (int iy = loy; iy <= hiy; iy++) {
                bool fxy = fx || (iy == cy - r) || (iy == cy + r);
                // z values to visit on this (ix,iy) column of the r-ring
                int zc[2];
                int nz = 0;
                if (fxy) {
                    zc[0] = loz; zc[1] = hiz; nz = -1;   // full range marker
                } else {
                    if (cz - r >= loz) zc[nz++] = cz - r;
                    if (r > 0 && cz + r <= hiz) zc[nz++] = cz + r;
                }
                int zi0 = (nz == -1) ? loz : 0;
                int zi1 = (nz == -1) ? hiz : nz - 1;
                for (int zi = zi0; zi <= zi1; zi++) {
                    int iz = (nz == -1) ? zi : zc[zi];
                    int cell = (ix * G_ + iy) * G_ + iz;
                    int s0  = g_cellstart[cbase + cell];
                    int cnt = g_cellcnt [cbase + cell];
                    int base = pbase + s0;
                    for (int j = 0; j < cnt; j++) {
                        float4 c = g_pts4[base + j];
                        float dx = c.x - qx, dy = c.y - qy, dz = c.z - qz;
                        float d = fmaf(dz, dz, fmaf(dy, dy, dx * dx));
                        if (d < rootv) {
                            int hh = 0;
                            for (;;) {
                                int l = 2 * hh + 1;
                                if (l >= K_) break;
                                float dc = hD[l * KNN_BT + t];
                                int child = l;
                                if (l + 1 < K_) {
                                    float dr = hD[(l + 1) * KNN_BT + t];
                                    if (dr > dc) { dc = dr; child = l + 1; }
                                }
                                if (dc <= d) break;
                                hD[hh * KNN_BT + t] = dc;
                                hI[hh * KNN_BT + t] = hI[child * KNN_BT + t];
                                hh = child;
                            }
                            hD[hh * KNN_BT + t] = d;
                            hI[hh * KNN_BT + t] = base + j;   // sorted position
                            rootv = hD[t];
                        }
                    }
                }
            }
        }

        bool all = (lox == 0 && hix == G_ - 1 && loy == 0 && hiy == G_ - 1 &&
                    loz == 0 && hiz == G_ - 1);
        if (rootv < CUDART_INF_F) {      // all 36 slots hold real candidates
            float d1 = (lox > 0)      ? (qx - (float)lox * h)        : 1e9f;
            float d2 = (hix < G_ - 1) ? ((float)(hix + 1) * h - qx)  : 1e9f;
            float d3 = (loy > 0)      ? (qy - (float)loy * h)        : 1e9f;
            float d4 = (hiy < G_ - 1) ? ((float)(hiy + 1) * h - qy)  : 1e9f;
            float d5 = (loz > 0)      ? (qz - (float)loz * h)        : 1e9f;
            float d6 = (hiz < G_ - 1) ? ((float)(hiz + 1) * h - qz)  : 1e9f;
            float dmin = fminf(fminf(fminf(d1, d2), fminf(d3, d4)), fminf(d5, d6));
            if (rootv + 1e-6f <= dmin * dmin) break;
        }
        if (all) break;
    }

    #pragma unroll
    for (int s = 0; s < K_; s++) g_nbr[(size_t)p * K_ + s] = hI[s * KNN_BT + t];
}

// ============================================================================
// Kernel: vector attention accumulate. Warp per query (sorted order: neighbors
// spatially local -> cache hits). 4 channels/lane, softmax denom via shfl.
// ============================================================================
__global__ void attn_kernel() {
    int gw   = (blockIdx.x * blockDim.x + threadIdx.x) >> 5;
    int lane = threadIdx.x & 31;
    if (gw >= BN_) return;
    size_t q = (size_t)gw;

    float4 eq = *(const float4*)&g_EQ[q * C_ + 4 * lane];
    int i0 = g_nbr[q * K_ + lane];
    int i1 = (lane < K_ - 32) ? g_nbr[q * K_ + 32 + lane] : 0;

    float4 acc = make_float4(0.f, 0.f, 0.f, 0.f);
    #pragma unroll 4
    for (int k = 0; k < K_; k++) {
        int j = (k < 32) ? __shfl_sync(0xffffffffu, i0, k)
                         : __shfl_sync(0xffffffffu, i1, k - 32);
        float4 ep = *(const float4*)&g_EP[(size_t)j * C_ + 4 * lane];
        float4 v  = *(const float4*)&g_V [(size_t)j * C_ + 4 * lane];
        float wx = ep.x * eq.x, wy = ep.y * eq.y, wz = ep.z * eq.z, ww = ep.w * eq.w;
        float part = (wx + wy) + (wz + ww);
        part += __shfl_xor_sync(0xffffffffu, part, 16);
        part += __shfl_xor_sync(0xffffffffu, part, 8);
        part += __shfl_xor_sync(0xffffffffu, part, 4);
        part += __shfl_xor_sync(0xffffffffu, part, 2);
        part += __shfl_xor_sync(0xffffffffu, part, 1);
        float rinv = __fdividef(1.0f, part);
        acc.x = fmaf(v.x, wx * rinv, acc.x);
        acc.y = fmaf(v.y, wy * rinv, acc.y);
        acc.z = fmaf(v.z, wz * rinv, acc.z);
        acc.w = fmaf(v.w, ww * rinv, acc.w);
    }
    *(float4*)&g_mid[q * C_ + 4 * lane] = acc;
}

// ============================================================================
// Kernel: output projection  out[pid[q]] = mid[q] @ Ws^T + bs.
// Ws cached in smem transposed [c][d] (stride 132), 8 queries per warp.
// ============================================================================
#define WS_STRIDE 132
#define OUT_SMEM  ((C_ * WS_STRIDE + 8 * C_ * 9) * 4)

__global__ void outproj_kernel(const float* __restrict__ Ws,
                               const float* __restrict__ bs,
                               float* __restrict__ out) {
    extern __shared__ float sm[];
    float* sWs  = sm;                    // [c][d] stride WS_STRIDE
    float* sMid = sm + C_ * WS_STRIDE;   // [warp][c][9]

    int t = threadIdx.x, w = t >> 5, lane = t & 31;
    for (int i = t; i < C_ * C_; i += 256) {
        int d = i >> 7, c = i & 127;
        sWs[c * WS_STRIDE + d] = Ws[i];
    }
    __syncthreads();

    float4 bs4 = *(const float4*)&bs[4 * lane];
    float* smw = sMid + w * C_ * 9;
    int gw = blockIdx.x * 8 + w;                 // 2048 warps total

    for (int itq = 0; itq < 2; itq++) {
        int q0 = (gw + itq * 2048) * 8;
        #pragma unroll
        for (int p = 0; p < 8; p++) {
            float4 m4 = *(const float4*)&g_mid[(size_t)(q0 + p) * C_ + 4 * lane];
            smw[(4 * lane + 0) * 9 + p] = m4.x;
            smw[(4 * lane + 1) * 9 + p] = m4.y;
            smw[(4 * lane + 2) * 9 + p] = m4.z;
            smw[(4 * lane + 3) * 9 + p] = m4.w;
        }
        __syncwarp();
        float4 acc[8];
        #pragma unroll
        for (int p = 0; p < 8; p++) acc[p] = bs4;
        for (int c = 0; c < C_; c++) {
            float4 wr = *(float4*)&sWs[c * WS_STRIDE + 4 * lane];
            #pragma unroll
            for (int p = 0; p < 8; p++) {
                float mc = smw[c * 9 + p];
                acc[p].x = fmaf(wr.x, mc, acc[p].x);
                acc[p].y = fmaf(wr.y, mc, acc[p].y);
                acc[p].z = fmaf(wr.z, mc, acc[p].z);
                acc[p].w = fmaf(wr.w, mc, acc[p].w);
            }
        }
        #pragma unroll
        for (int p = 0; p < 8; p++) {
            size_t row = (size_t)g_pid[q0 + p];     // back to original order
            *(float4*)&out[row * C_ + 4 * lane] = acc[p];
        }
        __syncwarp();
    }
}

// ============================================================================
extern "C" void kernel_launch(void* const* d_in, const int* in_sizes, int n_in,
                              void* d_out, int out_size) {
    const float* feat = (const float*)d_in[0];
    const float* xyz  = (const float*)d_in[1];
    const float* Wr   = (const float*)d_in[2];
    const float* br   = (const float*)d_in[3];
    const float* Wv   = (const float*)d_in[4];
    const float* bv   = (const float*)d_in[5];
    const float* Ws   = (const float*)d_in[6];
    const float* bs   = (const float*)d_in[7];
    float* out = (float*)d_out;

    cudaFuncSetAttribute(prep_kernel, cudaFuncAttributeMaxDynamicSharedMemorySize, PREP_SMEM);
    cudaFuncSetAttribute(outproj_kernel, cudaFuncAttributeMaxDynamicSharedMemorySize, OUT_SMEM);

    void* ccnt;
    cudaGetSymbolAddress(&ccnt, g_cellcnt);
    cudaMemsetAsync(ccnt, 0, B_ * GC_ * sizeof(int));

    // grid build
    cellassign_kernel<<<BN_ / 256, 256>>>(xyz);
    scan_kernel<<<B_, 1024>>>();
    scatter_kernel<<<BN_ / 256, 256>>>(xyz);
    sortfix_kernel<<<B_ * GC_ / 256, 256>>>();

    // per-point EP/EQ/V (written in sorted order)
    prep_kernel<<<BN_ / 128, 128, PREP_SMEM>>>(feat, xyz, Wr, br, Wv, bv);

    // exact 36-NN over the grid
    knnq_kernel<<<BN_ / KNN_BT, KNN_BT>>>();

    // vector attention accumulate
    attn_kernel<<<BN_ / 8, 256>>>();

    // output projection (+ scatter back to original order)
    outproj_kernel<<<256, 256, OUT_SMEM>>>(Ws, bs, out);
}

// round 5
// speedup vs baseline: 3.6596x; 1.0996x over previous
#include <cuda_runtime.h>
#include <cuda_bf16.h>
#include <math_constants.h>

// Problem constants (fixed by setup_inputs)
#define B_   4
#define N_   8192
#define BN_  (B_ * N_)      // 32768 points
#define DIN  64
#define DPRE 67             // feature(64) + xyz(3)
#define C_   128            // D_OUT
#define K_   36

// spatial grid
#define G_   16
#define GC_  (G_ * G_ * G_)   // 4096 cells per batch

// ---------------- device scratch (no allocations allowed) ----------------
__device__ float  g_EP [BN_ * C_];   // exp(Wr_left @ pre)           (sorted order)
__device__ float  g_EQ [BN_ * C_];   // exp((Wr_r - Wr_l) @ pre + br)(sorted order)
__device__ float  g_V  [BN_ * C_];   // relu(Wv @ pre + bv)          (sorted order)
__device__ float  g_mid[BN_ * C_];   // attention output             (sorted order)
__device__ int    g_nbr[BN_ * K_];   // knn neighbor SORTED positions
__device__ int    g_cellcnt [B_ * GC_];
__device__ int    g_cellstart[B_ * GC_];
__device__ int    g_cellid[BN_];     // per original point: within-batch cell
__device__ int    g_rank  [BN_];     // atomic rank within cell (pre-sort)
__device__ float4 g_pts4 [BN_];      // sorted points (x,y,z,pad)
__device__ int    g_pid  [BN_];      // sorted pos -> original global id
__device__ int    g_spos [BN_];      // original global id -> sorted pos

// ---------------- fast exp (FMA pipe) ------------------------------------
__device__ __forceinline__ float fast_exp(float x) {
    float y = x * 1.4426950408889634f;      // x * log2(e)
    int   e = __float2int_rn(y);
    float f = y - (float)e;                 // f in [-0.5, 0.5]
    float p =            1.5403530393381609e-4f;
    p = fmaf(p, f, 1.3333558146428443e-3f);
    p = fmaf(p, f, 9.6181291076284770e-3f);
    p = fmaf(p, f, 5.5504108664821580e-2f);
    p = fmaf(p, f, 2.4022650695910070e-1f);
    p = fmaf(p, f, 6.9314718055994530e-1f);
    p = fmaf(p, f, 1.0f);
    float s = __int_as_float((e + 127) << 23);
    return p * s;
}

// ============================================================================
// Grid build step 1: cell assignment + per-cell atomic rank
// ============================================================================
__global__ void cellassign_kernel(const float* __restrict__ xyz) {
    int m = blockIdx.x * blockDim.x + threadIdx.x;
    if (m >= BN_) return;
    int b = m >> 13;
    float x = xyz[(size_t)m * 3 + 0];
    float y = xyz[(size_t)m * 3 + 1];
    float z = xyz[(size_t)m * 3 + 2];
    int cx = min(G_ - 1, max(0, (int)(x * (float)G_)));
    int cy = min(G_ - 1, max(0, (int)(y * (float)G_)));
    int cz = min(G_ - 1, max(0, (int)(z * (float)G_)));
    int cell = (cx * G_ + cy) * G_ + cz;
    int r = atomicAdd(&g_cellcnt[b * GC_ + cell], 1);
    g_cellid[m] = cell;
    g_rank[m] = r;
}

// ============================================================================
// Grid build step 2: exclusive prefix sum over 4096 cells (one block / batch)
// ============================================================================
__global__ void scan_kernel() {
    __shared__ int s[1024];
    int b = blockIdx.x;
    int t = threadIdx.x;
    int c0 = g_cellcnt[b * GC_ + 4 * t + 0];
    int c1 = g_cellcnt[b * GC_ + 4 * t + 1];
    int c2 = g_cellcnt[b * GC_ + 4 * t + 2];
    int c3 = g_cellcnt[b * GC_ + 4 * t + 3];
    int tot = c0 + c1 + c2 + c3;
    s[t] = tot;
    __syncthreads();
    for (int off = 1; off < 1024; off <<= 1) {
        int x = (t >= off) ? s[t - off] : 0;
        __syncthreads();
        s[t] += x;
        __syncthreads();
    }
    int excl = s[t] - tot;
    g_cellstart[b * GC_ + 4 * t + 0] = excl;
    g_cellstart[b * GC_ + 4 * t + 1] = excl + c0;
    g_cellstart[b * GC_ + 4 * t + 2] = excl + c0 + c1;
    g_cellstart[b * GC_ + 4 * t + 3] = excl + c0 + c1 + c2;
}

// ============================================================================
// Grid build step 3: scatter points into cell-sorted layout
// ============================================================================
__global__ void scatter_kernel(const float* __restrict__ xyz) {
    int m = blockIdx.x * blockDim.x + threadIdx.x;
    if (m >= BN_) return;
    int b = m >> 13;
    int cell = g_cellid[m];
    int p = b * N_ + g_cellstart[b * GC_ + cell] + g_rank[m];
    float x = xyz[(size_t)m * 3 + 0];
    float y = xyz[(size_t)m * 3 + 1];
    float z = xyz[(size_t)m * 3 + 2];
    g_pts4[p] = make_float4(x, y, z, 0.0f);
    g_pid[p] = m;
}

// ============================================================================
// Grid build step 4: determinism fix-up (atomic rank order varies per replay;
// insertion-sort each cell by original index so layout is replay-invariant).
// ============================================================================
__global__ void sortfix_kernel() {
    int i = blockIdx.x * blockDim.x + threadIdx.x;
    if (i >= B_ * GC_) return;
    int b = i / GC_;
    int cell = i - b * GC_;
    int start = b * N_ + g_cellstart[b * GC_ + cell];
    int cnt = g_cellcnt[b * GC_ + cell];
    for (int a = 1; a < cnt; a++) {
        int pid = g_pid[start + a];
        float4 pt = g_pts4[start + a];
        int j = a - 1;
        while (j >= 0 && g_pid[start + j] > pid) {
            g_pid[start + j + 1]  = g_pid[start + j];
            g_pts4[start + j + 1] = g_pts4[start + j];
            j--;
        }
        g_pid[start + j + 1]  = pid;
        g_pts4[start + j + 1] = pt;
    }
    for (int a = 0; a < cnt; a++) g_spos[g_pid[start + a]] = start + a;
}

// ============================================================================
// Kernel: per-point preprocessing (EP/EQ/V), written in SORTED order for the
// attention gather's locality. Weights staged in smem transposed to [d][c].
// ============================================================================
#define PREP_SMEM ((3 * DPRE * C_ + 4 * 4 * 68) * 4)

__global__ void prep_kernel(const float* __restrict__ feat,
                            const float* __restrict__ xyz,
                            const float* __restrict__ Wr,
                            const float* __restrict__ br,
                            const float* __restrict__ Wv,
                            const float* __restrict__ bv) {
    extern __shared__ float sm[];
    float* sWA = sm;                       // Wr_left   [d][c]
    float* sWB = sm + DPRE * C_;           // Wr_right  [d][c] (then -= left)
    float* sWC = sm + 2 * DPRE * C_;       // Wv        [d][c]
    float* sPre = sm + 3 * DPRE * C_;      // [warp][4][68]

    int t = threadIdx.x;
    for (int i = t; i < C_ * 134; i += 128) {
        int c = i / 134, dd = i % 134;
        float v = Wr[i];
        if (dd < DPRE) sWA[dd * C_ + c] = v;
        else           sWB[(dd - DPRE) * C_ + c] = v;
    }
    for (int i = t; i < C_ * DPRE; i += 128) {
        int c = i / DPRE, d = i % DPRE;
        sWC[d * C_ + c] = Wv[i];
    }
    __syncthreads();
    for (int i = t; i < DPRE * C_; i += 128) sWB[i] -= sWA[i];
    __syncthreads();

    int w = t >> 5, lane = t & 31;
    float4 br4 = *(const float4*)&br[4 * lane];
    float4 bv4 = *(const float4*)&bv[4 * lane];
    float* spw = sPre + w * 4 * 68;

    int base = blockIdx.x * 128 + w * 32;   // 32 points per warp
    for (int it = 0; it < 8; it++) {
        int m0 = base + it * 4;
        #pragma unroll
        for (int p = 0; p < 4; p++) {
            int m = m0 + p;
            spw[p * 68 + lane]      = feat[(size_t)m * 64 + lane];
            spw[p * 68 + 32 + lane] = feat[(size_t)m * 64 + 32 + lane];
            if (lane < 3) spw[p * 68 + 64 + lane] = xyz[(size_t)m * 3 + lane];
        }
        __syncwarp();

        float aP[4][4], aQ[4][4], aV[4][4];
        #pragma unroll
        for (int p = 0; p < 4; p++)
            #pragma unroll
            for (int r = 0; r < 4; r++) { aP[p][r] = 0.f; aQ[p][r] = 0.f; aV[p][r] = 0.f; }

        for (int d = 0; d < DPRE; d++) {
            float4 wa = *(float4*)&sWA[d * C_ + 4 * lane];
            float4 wb = *(float4*)&sWB[d * C_ + 4 * lane];
            float4 wc = *(float4*)&sWC[d * C_ + 4 * lane];
            #pragma unroll
            for (int p = 0; p < 4; p++) {
                float x = spw[p * 68 + d];
                aP[p][0] = fmaf(wa.x, x, aP[p][0]);
                aP[p][1] = fmaf(wa.y, x, aP[p][1]);
                aP[p][2] = fmaf(wa.z, x, aP[p][2]);
                aP[p][3] = fmaf(wa.w, x, aP[p][3]);
                aQ[p][0] = fmaf(wb.x, x, aQ[p][0]);
                aQ[p][1] = fmaf(wb.y, x, aQ[p][1]);
                aQ[p][2] = fmaf(wb.z, x, aQ[p][2]);
                aQ[p][3] = fmaf(wb.w, x, aQ[p][3]);
                aV[p][0] = fmaf(wc.x, x, aV[p][0]);
                aV[p][1] = fmaf(wc.y, x, aV[p][1]);
                aV[p][2] = fmaf(wc.z, x, aV[p][2]);
                aV[p][3] = fmaf(wc.w, x, aV[p][3]);
            }
        }
        #pragma unroll
        for (int p = 0; p < 4; p++) {
            size_t sp = (size_t)g_spos[m0 + p];     // sorted destination
            float4 ep, eq, vv;
            ep.x = fast_exp(aP[p][0]); ep.y = fast_exp(aP[p][1]);
            ep.z = fast_exp(aP[p][2]); ep.w = fast_exp(aP[p][3]);
            eq.x = fast_exp(aQ[p][0] + br4.x); eq.y = fast_exp(aQ[p][1] + br4.y);
            eq.z = fast_exp(aQ[p][2] + br4.z); eq.w = fast_exp(aQ[p][3] + br4.w);
            vv.x = fmaxf(aV[p][0] + bv4.x, 0.f); vv.y = fmaxf(aV[p][1] + bv4.y, 0.f);
            vv.z = fmaxf(aV[p][2] + bv4.z, 0.f); vv.w = fmaxf(aV[p][3] + bv4.w, 0.f);
            *(float4*)&g_EP[sp * C_ + 4 * lane] = ep;
            *(float4*)&g_EQ[sp * C_ + 4 * lane] = eq;
            *(float4*)&g_V [sp * C_ + 4 * lane] = vv;
        }
        __syncwarp();
    }
}

// ============================================================================
// Kernel: exact 36-NN, WARP PER QUERY.
// Box scan (2r+1)^3 as (ix,iy) columns; z-range in a column is one contiguous
// span of sorted points -> coalesced loads, round-robin lane assignment.
// Each lane keeps a register-resident sorted top-12 (unrolled insertion).
// Exactness: count candidates with d <= dmin^2 (dmin = nearest unclipped box
// face); count >= 36 proves the true top-36 is inside the box. Else expand.
// Merge: 36x warp extract-min via __reduce_min_sync, deterministic tie-break
// on sorted position.
// ============================================================================
#define LLEN 12
#define INFBITS 0x7f800000u
#define EXHBITS 0xffffffffu

__global__ void knnq_kernel() {
    int lane = threadIdx.x & 31;
    int q = blockIdx.x * (blockDim.x >> 5) + (threadIdx.x >> 5);  // sorted pos
    int b = q >> 13;

    float4 me = g_pts4[q];
    float qx = me.x, qy = me.y, qz = me.z;
    int cx = min(G_ - 1, max(0, (int)(qx * (float)G_)));
    int cy = min(G_ - 1, max(0, (int)(qy * (float)G_)));
    int cz = min(G_ - 1, max(0, (int)(qz * (float)G_)));

    const float h = 1.0f / (float)G_;
    const int cbase = b * GC_;
    const int pbase = b * N_;

    unsigned ld[LLEN];     // distance bits (sorted ascending)
    int      lp[LLEN];     // global sorted position of candidate

    for (int r = 2; ; r++) {
        #pragma unroll
        for (int s = 0; s < LLEN; s++) { ld[s] = INFBITS; lp[s] = -1; }

        int lox = max(cx - r, 0), hix = min(cx + r, G_ - 1);
        int loy = max(cy - r, 0), hiy = min(cy + r, G_ - 1);
        int loz = max(cz - r, 0), hiz = min(cz + r, G_ - 1);

        float d1 = (lox > 0)      ? (qx - (float)lox * h)        : 1e9f;
        float d2 = (hix < G_ - 1) ? ((float)(hix + 1) * h - qx)  : 1e9f;
        float d3 = (loy > 0)      ? (qy - (float)loy * h)        : 1e9f;
        float d4 = (hiy < G_ - 1) ? ((float)(hiy + 1) * h - qy)  : 1e9f;
        float d5 = (loz > 0)      ? (qz - (float)loz * h)        : 1e9f;
        float d6 = (hiz < G_ - 1) ? ((float)(hiz + 1) * h - qz)  : 1e9f;
        float dmin = fminf(fminf(fminf(d1, d2), fminf(d3, d4)), fminf(d5, d6));
        float dth = fminf(dmin * dmin, 1e9f);

        int cnt_near = 0;
        int streamoff = 0;

        for (int ix = lox; ix <= hix; ix++) {
            for (int iy = loy; iy <= hiy; iy++) {
                int col = (ix * G_ + iy) * G_;
                int s0  = g_cellstart[cbase + col + loz];
                int e0  = g_cellstart[cbase + col + hiz] + g_cellcnt[cbase + col + hiz];
                int len = e0 - s0;
                int base = pbase + s0;
                for (int j = (lane - streamoff) & 31; j < len; j += 32) {
                    float4 c = g_pts4[base + j];
                    float dx = c.x - qx, dy = c.y - qy, dz = c.z - qz;
                    float d = fmaf(dz, dz, fmaf(dy, dy, dx * dx));
                    cnt_near += (d <= dth) ? 1 : 0;
                    unsigned db = __float_as_uint(d);
                    if (db < ld[LLEN - 1]) {
                        unsigned cd = db; int cp = base + j;
                        #pragma unroll
                        for (int s = 0; s < LLEN; s++) {
                            unsigned od = ld[s]; int op = lp[s];
                            if (cd < od) { ld[s] = cd; lp[s] = cp; cd = od; cp = op; }
                        }
                    }
                }
                streamoff += len;
            }
        }

        unsigned tot = __reduce_add_sync(0xffffffffu, (unsigned)cnt_near);
        bool all = (lox == 0 && hix == G_ - 1 && loy == 0 && hiy == G_ - 1 &&
                    loz == 0 && hiz == G_ - 1);
        if (tot >= (unsigned)K_ || all) break;
    }

    // merge: 36 warp extract-mins
    for (int s = 0; s < K_; s++) {
        unsigned myh = ld[0];
        unsigned m = __reduce_min_sync(0xffffffffu, myh);
        unsigned mask = __ballot_sync(0xffffffffu, myh == m);
        if (__popc(mask) > 1) {
            // deterministic tie-break: smallest sorted position wins
            unsigned pp = (myh == m) ? (unsigned)lp[0] : 0xffffffffu;
            unsigned pmin = __reduce_min_sync(0xffffffffu, pp);
            mask = __ballot_sync(0xffffffffu, (myh == m) && ((unsigned)lp[0] == pmin));
        }
        int leader = __ffs(mask) - 1;
        if (lane == leader) {
            g_nbr[(size_t)q * K_ + s] = lp[0];
            #pragma unroll
            for (int t2 = 0; t2 < LLEN - 1; t2++) { ld[t2] = ld[t2 + 1]; lp[t2] = lp[t2 + 1]; }
            ld[LLEN - 1] = EXHBITS;
        }
    }
}

// ============================================================================
// Kernel: vector attention accumulate. Warp per query (sorted order: neighbors
// spatially local -> cache hits). 4 channels/lane, softmax denom via shfl.
// ============================================================================
__global__ void attn_kernel() {
    int gw   = (blockIdx.x * blockDim.x + threadIdx.x) >> 5;
    int lane = threadIdx.x & 31;
    if (gw >= BN_) return;
    size_t q = (size_t)gw;

    float4 eq = *(const float4*)&g_EQ[q * C_ + 4 * lane];
    int i0 = g_nbr[q * K_ + lane];
    int i1 = (lane < K_ - 32) ? g_nbr[q * K_ + 32 + lane] : 0;

    float4 acc = make_float4(0.f, 0.f, 0.f, 0.f);
    #pragma unroll 4
    for (int k = 0; k < K_; k++) {
        int j = (k < 32) ? __shfl_sync(0xffffffffu, i0, k)
                         : __shfl_sync(0xffffffffu, i1, k - 32);
        float4 ep = *(const float4*)&g_EP[(size_t)j * C_ + 4 * lane];
        float4 v  = *(const float4*)&g_V [(size_t)j * C_ + 4 * lane];
        float wx = ep.x * eq.x, wy = ep.y * eq.y, wz = ep.z * eq.z, ww = ep.w * eq.w;
        float part = (wx + wy) + (wz + ww);
        part += __shfl_xor_sync(0xffffffffu, part, 16);
        part += __shfl_xor_sync(0xffffffffu, part, 8);
        part += __shfl_xor_sync(0xffffffffu, part, 4);
        part += __shfl_xor_sync(0xffffffffu, part, 2);
        part += __shfl_xor_sync(0xffffffffu, part, 1);
        float rinv = __fdividef(1.0f, part);
        acc.x = fmaf(v.x, wx * rinv, acc.x);
        acc.y = fmaf(v.y, wy * rinv, acc.y);
        acc.z = fmaf(v.z, wz * rinv, acc.z);
        acc.w = fmaf(v.w, ww * rinv, acc.w);
    }
    *(float4*)&g_mid[q * C_ + 4 * lane] = acc;
}

// ============================================================================
// Kernel: output projection  out[pid[q]] = mid[q] @ Ws^T + bs.
// Ws cached in smem transposed [c][d] (stride 132), 8 queries per warp.
// ============================================================================
#define WS_STRIDE 132
#define OUT_SMEM  ((C_ * WS_STRIDE + 8 * C_ * 9) * 4)

__global__ void outproj_kernel(const float* __restrict__ Ws,
                               const float* __restrict__ bs,
                               float* __restrict__ out) {
    extern __shared__ float sm[];
    float* sWs  = sm;                    // [c][d] stride WS_STRIDE
    float* sMid = sm + C_ * WS_STRIDE;   // [warp][c][9]

    int t = threadIdx.x, w = t >> 5, lane = t & 31;
    for (int i = t; i < C_ * C_; i += 256) {
        int d = i >> 7, c = i & 127;
        sWs[c * WS_STRIDE + d] = Ws[i];
    }
    __syncthreads();

    float4 bs4 = *(const float4*)&bs[4 * lane];
    float* smw = sMid + w * C_ * 9;
    int gw = blockIdx.x * 8 + w;                 // 2048 warps total

    for (int itq = 0; itq < 2; itq++) {
        int q0 = (gw + itq * 2048) * 8;
        #pragma unroll
        for (int p = 0; p < 8; p++) {
            float4 m4 = *(const float4*)&g_mid[(size_t)(q0 + p) * C_ + 4 * lane];
            smw[(4 * lane + 0) * 9 + p] = m4.x;
            smw[(4 * lane + 1) * 9 + p] = m4.y;
            smw[(4 * lane + 2) * 9 + p] = m4.z;
            smw[(4 * lane + 3) * 9 + p] = m4.w;
        }
        __syncwarp();
        float4 acc[8];
        #pragma unroll
        for (int p = 0; p < 8; p++) acc[p] = bs4;
        for (int c = 0; c < C_; c++) {
            float4 wr = *(float4*)&sWs[c * WS_STRIDE + 4 * lane];
            #pragma unroll
            for (int p = 0; p < 8; p++) {
                float mc = smw[c * 9 + p];
                acc[p].x = fmaf(wr.x, mc, acc[p].x);
                acc[p].y = fmaf(wr.y, mc, acc[p].y);
                acc[p].z = fmaf(wr.z, mc, acc[p].z);
                acc[p].w = fmaf(wr.w, mc, acc[p].w);
            }
        }
        #pragma unroll
        for (int p = 0; p < 8; p++) {
            size_t row = (size_t)g_pid[q0 + p];     // back to original order
            *(float4*)&out[row * C_ + 4 * lane] = acc[p];
        }
        __syncwarp();
    }
}

// ============================================================================
extern "C" void kernel_launch(void* const* d_in, const int* in_sizes, int n_in,
                              void* d_out, int out_size) {
    const float* feat = (const float*)d_in[0];
    const float* xyz  = (const float*)d_in[1];
    const float* Wr   = (const float*)d_in[2];
    const float* br   = (const float*)d_in[3];
    const float* Wv   = (const float*)d_in[4];
    const float* bv   = (const float*)d_in[5];
    const float* Ws   = (const float*)d_in[6];
    const float* bs   = (const float*)d_in[7];
    float* out = (float*)d_out;

    cudaFuncSetAttribute(prep_kernel, cudaFuncAttributeMaxDynamicSharedMemorySize, PREP_SMEM);
    cudaFuncSetAttribute(outproj_kernel, cudaFuncAttributeMaxDynamicSharedMemorySize, OUT_SMEM);

    void* ccnt;
    cudaGetSymbolAddress(&ccnt, g_cellcnt);
    cudaMemsetAsync(ccnt, 0, B_ * GC_ * sizeof(int));

    // grid build
    cellassign_kernel<<<BN_ / 256, 256>>>(xyz);
    scan_kernel<<<B_, 1024>>>();
    scatter_kernel<<<BN_ / 256, 256>>>(xyz);
    sortfix_kernel<<<B_ * GC_ / 256, 256>>>();

    // per-point EP/EQ/V (written in sorted order)
    prep_kernel<<<BN_ / 128, 128, PREP_SMEM>>>(feat, xyz, Wr, br, Wv, bv);

    // exact 36-NN, warp per query
    knnq_kernel<<<BN_ / 8, 256>>>();

    // vector attention accumulate
    attn_kernel<<<BN_ / 8, 256>>>();

    // output projection (+ scatter back to original order)
    outproj_kernel<<<256, 256, OUT_SMEM>>>(Ws, bs, out);
}